// round 13
// baseline (speedup 1.0000x reference)
#include <cuda_runtime.h>
#include <cstdint>
#include <math.h>

#define NATOM 50000
#define AFEA  64
#define FAN   169
#define CO    128
#define NROW  600000
#define TROWS 48          // rows per tile = 4 atoms exactly
#define NTT   12500       // NROW / 48
#define NT0   391         // ceil(NATOM/128)
#define KGB   444         // k1 grid (3 CTAs/SM)
#define XSTR  100         // xs word stride per k-row: 48 rows * 2 (dup) + 4 pad
#define WSTR  132         // ws word stride per k-row: 128 + 4 pad

// -------- scratch (device globals; allocation is forbidden) --------
__device__ float  g_PQ[NATOM * 256];          // [n][0:128]=P(self), [128:256]=Q(nbr)
__device__ float  g_sumed[NATOM * AFEA];
__device__ double g_p1s[KGB * CO],  g_p1q[KGB * CO];
__device__ double g_p2s[KGB * AFEA], g_p2q[KGB * AFEA];
__device__ float  g_scale1[CO], g_shift1[CO], g_scale2[AFEA], g_shift2[AFEA];

// -------- packed f32x2 helpers (sm_103a) --------
typedef unsigned long long ull_t;
#define FMA2(d, a, b, c) asm("fma.rn.f32x2 %0, %1, %2, %3;" : "=l"(d) : "l"(a), "l"(b), "l"(c))
__device__ __forceinline__ ull_t dupf(float x) {
    ull_t d; unsigned u = __float_as_uint(x);
    asm("mov.b64 %0, {%1, %2};" : "=l"(d) : "r"(u), "r"(u));
    return d;
}
__device__ __forceinline__ void unpk(float& lo, float& hi, ull_t v) {
    unsigned a, b;
    asm("mov.b64 {%0, %1}, %2;" : "=r"(a), "=r"(b) : "l"(v));
    lo = __uint_as_float(a); hi = __uint_as_float(b);
}
__device__ __forceinline__ float sigm(float x) { return __fdividef(1.0f, 1.0f + __expf(-x)); }
__device__ __forceinline__ float splus(float x) {
    return fmaxf(x, 0.0f) + __logf(1.0f + __expf(-fabsf(x)));
}

// -------- k0: per-atom projections P,Q (proven config from round 12) --------
__device__ __forceinline__ int wsw(int c) {
    return (((c & 7) >> 2) << 6) + ((c >> 3) << 2) + (c & 3);
}
__global__ __launch_bounds__(256, 2) void k0_proj(const float* __restrict__ atom,
                                                  const float* __restrict__ W) {
    __shared__ __align__(16) float ws[32 * 132];
    __shared__ __align__(16) float xs[32 * 136];
    const int tid = threadIdx.x;
    const int tc = tid & 15, tr = tid >> 4;
    const int r0 = blockIdx.x * 128;

    for (int h = 0; h < 2; ++h) {
        ull_t acc[8][4];
#pragma unroll
        for (int r = 0; r < 8; ++r)
#pragma unroll
            for (int c = 0; c < 4; ++c) acc[r][c] = 0ULL;

        for (int kc = 0; kc < 2; ++kc) {
            __syncthreads();
            for (int i = tid; i < 128 * 32; i += 256) {
                int row = i >> 5, kk = i & 31;
                int gr = r0 + row;
                xs[kk * 136 + row] = (gr < NATOM) ? atom[gr * AFEA + kc * 32 + kk] : 0.0f;
            }
            for (int i = tid; i < 128 * 32; i += 256) {
                int c = i >> 5, kk = i & 31;
                ws[kk * 132 + wsw(c)] = W[c * FAN + h * 64 + kc * 32 + kk];
            }
            __syncthreads();
#pragma unroll 4
            for (int kk = 0; kk < 32; ++kk) {
                const float* xr = &xs[kk * 136 + tr * 8];
                const float* wr = &ws[kk * 132 + tc * 4];
                float4 xa = *(const float4*)(xr);
                float4 xb = *(const float4*)(xr + 4);
                ulonglong2 wA = *(const ulonglong2*)(wr);
                ulonglong2 wB = *(const ulonglong2*)(wr + 64);
                float xr8[8] = {xa.x, xa.y, xa.z, xa.w, xb.x, xb.y, xb.z, xb.w};
#pragma unroll
                for (int r = 0; r < 8; ++r) {
                    ull_t xd = dupf(xr8[r]);
                    FMA2(acc[r][0], xd, wA.x, acc[r][0]);
                    FMA2(acc[r][1], xd, wA.y, acc[r][1]);
                    FMA2(acc[r][2], xd, wB.x, acc[r][2]);
                    FMA2(acc[r][3], xd, wB.y, acc[r][3]);
                }
            }
        }
#pragma unroll
        for (int r = 0; r < 8; ++r) {
            int g = r0 + tr * 8 + r;
            if (g < NATOM) {
                float v[8];
#pragma unroll
                for (int c = 0; c < 4; ++c) unpk(v[2 * c], v[2 * c + 1], acc[r][c]);
                float* dst = &g_PQ[(size_t)g * 256 + h * 128 + tc * 8];
                *(float4*)dst       = make_float4(v[0], v[1], v[2], v[3]);
                *(float4*)(dst + 4) = make_float4(v[4], v[5], v[6], v[7]);
            }
        }
    }
}

// -------- k1: edge GEMM, two passes sharing one body --------
// Thread map: tr = tid&7 (6 rows each, 48 rows), tc = tid>>3 (cols tc*2,+1 and 64+tc*2,+1).
// x duplicated in smem -> 3 LDS.128; w natural col-pairs -> 2 LDS.64; 12 FMA2/k.
// PASS2=false: gated -> BN1 partials.  PASS2=true: BN1 affine -> sigm*splus -> atom sum + BN2.
template <bool PASS2>
__global__ __launch_bounds__(256, 3) void k1_pass(const float* __restrict__ nbr,
                                                  const int* __restrict__ idx,
                                                  const float* __restrict__ W,
                                                  const float* __restrict__ bvec) {
    __shared__ __align__(16) float ws[41 * WSTR];   // 21.6 KB
    __shared__ __align__(16) float xs[41 * XSTR];   // 16.4 KB (x duplicated)
    __shared__ int sidx[TROWS];
    __shared__ double reds[128], redq[128];
    const int tid = threadIdx.x;
    const int tr = tid & 7, tc = tid >> 3;          // tr: 8 row-groups, tc: 32 col-groups

    if (tid < 128) { reds[tid] = 0.0; redq[tid] = 0.0; }
    for (int i = tid; i < 41 * 128; i += 256) {     // edge weights once, natural layout
        int c = i / 41, kk = i - c * 41;
        ws[kk * WSTR + c] = W[c * FAN + 128 + kk];
    }
    // this thread's 4 columns: filter f0,f1 = tc*2,tc*2+1 ; core c0,c1 = 64+tc*2,65+tc*2
    float2 bvF = *(const float2*)&bvec[tc * 2];
    float2 bvC = *(const float2*)&bvec[64 + tc * 2];
    float2 scF, shF, scC, shC;
    if (PASS2) {
        scF = *(const float2*)&g_scale1[tc * 2];
        scC = *(const float2*)&g_scale1[64 + tc * 2];
        shF = *(const float2*)&g_shift1[tc * 2];
        shC = *(const float2*)&g_shift1[64 + tc * 2];
    }
    float fs[4], fq[4];
#pragma unroll
    for (int c = 0; c < 4; ++c) { fs[c] = 0.0f; fq[c] = 0.0f; }

    for (int t = blockIdx.x; t < NTT; t += KGB) {
        const int r0 = t * TROWS;
        __syncthreads();
        for (int i = tid; i < TROWS * 41; i += 256) {
            int row = i / 41, kk = i - row * 41;
            *(ull_t*)&xs[kk * XSTR + row * 2] = dupf(nbr[(size_t)r0 * 41 + i]);
        }
        if (tid < TROWS) sidx[tid] = idx[r0 + tid];
        __syncthreads();

        ull_t acc[6][2];
#pragma unroll
        for (int r = 0; r < 6; ++r) { acc[r][0] = 0ULL; acc[r][1] = 0ULL; }
#pragma unroll 4
        for (int kk = 0; kk < 41; ++kk) {
            const ulonglong2* xp = (const ulonglong2*)&xs[kk * XSTR + tr * 12];
            ulonglong2 x01 = xp[0], x23 = xp[1], x45 = xp[2];
            ull_t wF = *(const ull_t*)&ws[kk * WSTR + tc * 2];
            ull_t wC = *(const ull_t*)&ws[kk * WSTR + 64 + tc * 2];
            FMA2(acc[0][0], x01.x, wF, acc[0][0]); FMA2(acc[0][1], x01.x, wC, acc[0][1]);
            FMA2(acc[1][0], x01.y, wF, acc[1][0]); FMA2(acc[1][1], x01.y, wC, acc[1][1]);
            FMA2(acc[2][0], x23.x, wF, acc[2][0]); FMA2(acc[2][1], x23.x, wC, acc[2][1]);
            FMA2(acc[3][0], x23.y, wF, acc[3][0]); FMA2(acc[3][1], x23.y, wC, acc[3][1]);
            FMA2(acc[4][0], x45.x, wF, acc[4][0]); FMA2(acc[4][1], x45.x, wC, acc[4][1]);
            FMA2(acc[5][0], x45.y, wF, acc[5][0]); FMA2(acc[5][1], x45.y, wC, acc[5][1]);
        }

        // ---- epilogue: this thread's 6 rows are one half-atom ----
        const int atom = r0 / 12 + (tr >> 1);
        const float* Pb = &g_PQ[(size_t)atom * 256];
        float2 pF = *(const float2*)(Pb + tc * 2);
        float2 pC = *(const float2*)(Pb + 64 + tc * 2);
        float asum0 = 0.0f, asum1 = 0.0f;
#pragma unroll
        for (int r = 0; r < 6; ++r) {
            float vf0, vf1, vc0, vc1;
            unpk(vf0, vf1, acc[r][0]);
            unpk(vc0, vc1, acc[r][1]);
            const float* Qb = &g_PQ[(size_t)sidx[tr * 6 + r] * 256 + 128];
            float2 qF = *(const float2*)(Qb + tc * 2);
            float2 qC = *(const float2*)(Qb + 64 + tc * 2);
            vf0 += pF.x + qF.x + bvF.x;  vf1 += pF.y + qF.y + bvF.y;
            vc0 += pC.x + qC.x + bvC.x;  vc1 += pC.y + qC.y + bvC.y;
            if (!PASS2) {
                fs[0] += vf0; fq[0] += vf0 * vf0;
                fs[1] += vf1; fq[1] += vf1 * vf1;
                fs[2] += vc0; fq[2] += vc0 * vc0;
                fs[3] += vc1; fq[3] += vc1 * vc1;
            } else {
                float zf0 = vf0 * scF.x + shF.x, zf1 = vf1 * scF.y + shF.y;
                float zc0 = vc0 * scC.x + shC.x, zc1 = vc1 * scC.y + shC.y;
                asum0 += sigm(zf0) * splus(zc0);
                asum1 += sigm(zf1) * splus(zc1);
            }
        }
        if (PASS2) {
            // merge the two half-atoms: lanes tr and tr^1 share tc
            asum0 += __shfl_xor_sync(0xffffffffu, asum0, 1);
            asum1 += __shfl_xor_sync(0xffffffffu, asum1, 1);
            if (!(tr & 1)) {
                *(float2*)&g_sumed[(size_t)atom * 64 + tc * 2] = make_float2(asum0, asum1);
                fs[0] += asum0; fq[0] += asum0 * asum0;
                fs[1] += asum1; fq[1] += asum1 * asum1;
            }
        }
    }
    __syncthreads();
    if (!PASS2) {
        atomicAdd(&reds[tc * 2],      (double)fs[0]);
        atomicAdd(&redq[tc * 2],      (double)fq[0]);
        atomicAdd(&reds[tc * 2 + 1],  (double)fs[1]);
        atomicAdd(&redq[tc * 2 + 1],  (double)fq[1]);
        atomicAdd(&reds[64 + tc * 2],     (double)fs[2]);
        atomicAdd(&redq[64 + tc * 2],     (double)fq[2]);
        atomicAdd(&reds[64 + tc * 2 + 1], (double)fs[3]);
        atomicAdd(&redq[64 + tc * 2 + 1], (double)fq[3]);
        __syncthreads();
        if (tid < 128) {
            g_p1s[blockIdx.x * CO + tid] = reds[tid];
            g_p1q[blockIdx.x * CO + tid] = redq[tid];
        }
    } else {
        if (!(tr & 1)) {
            atomicAdd(&reds[tc * 2],     (double)fs[0]);
            atomicAdd(&redq[tc * 2],     (double)fq[0]);
            atomicAdd(&reds[tc * 2 + 1], (double)fs[1]);
            atomicAdd(&redq[tc * 2 + 1], (double)fq[1]);
        }
        __syncthreads();
        if (tid < 64) {
            g_p2s[blockIdx.x * AFEA + tid] = reds[tid];
            g_p2q[blockIdx.x * AFEA + tid] = redq[tid];
        }
    }
}

// -------- k2: finalize BN1 (one block per channel) --------
__global__ void k2_fin(const float* __restrict__ g1, const float* __restrict__ b1) {
    __shared__ double sd[256], sq[256];
    const int ch = blockIdx.x, t = threadIdx.x;
    double s = 0.0, q = 0.0;
    for (int b = t; b < KGB; b += 256) { s += g_p1s[b * CO + ch]; q += g_p1q[b * CO + ch]; }
    sd[t] = s; sq[t] = q;
    __syncthreads();
    for (int o = 128; o > 0; o >>= 1) {
        if (t < o) { sd[t] += sd[t + o]; sq[t] += sq[t + o]; }
        __syncthreads();
    }
    if (t == 0) {
        double mean = sd[0] / (double)NROW;
        double var  = sq[0] / (double)NROW - mean * mean;
        float inv = (float)(1.0 / sqrt(var + 1e-5));
        float sc = g1[ch] * inv;
        g_scale1[ch] = sc;
        g_shift1[ch] = b1[ch] - (float)mean * sc;
    }
}

// -------- k4: finalize BN2 (one block per channel) --------
__global__ void k4_fin(const float* __restrict__ g2, const float* __restrict__ b2) {
    __shared__ double sd[256], sq[256];
    const int ch = blockIdx.x, t = threadIdx.x;
    double s = 0.0, q = 0.0;
    for (int b = t; b < KGB; b += 256) { s += g_p2s[b * AFEA + ch]; q += g_p2q[b * AFEA + ch]; }
    sd[t] = s; sq[t] = q;
    __syncthreads();
    for (int o = 128; o > 0; o >>= 1) {
        if (t < o) { sd[t] += sd[t + o]; sq[t] += sq[t + o]; }
        __syncthreads();
    }
    if (t == 0) {
        double mean = sd[0] / (double)NATOM;
        double var  = sq[0] / (double)NATOM - mean * mean;
        float inv = (float)(1.0 / sqrt(var + 1e-5));
        float sc = g2[ch] * inv;
        g_scale2[ch] = sc;
        g_shift2[ch] = b2[ch] - (float)mean * sc;
    }
}

// -------- k5: final softplus --------
__global__ void k5_out(const float* __restrict__ atom, float* __restrict__ out) {
    int i = blockIdx.x * blockDim.x + threadIdx.x;
    if (i < NATOM * AFEA) {
        int a = i & 63;
        float v = atom[i] + g_sumed[i] * g_scale2[a] + g_shift2[a];
        out[i] = splus(v);
    }
}

extern "C" void kernel_launch(void* const* d_in, const int* in_sizes, int n_in,
                              void* d_out, int out_size) {
    const float* atom = (const float*)d_in[0];
    const float* nbr  = (const float*)d_in[1];
    const int*   idx  = (const int*)d_in[2];
    const float* W    = (const float*)d_in[3];
    const float* bvec = (const float*)d_in[4];
    const float* bn1g = (const float*)d_in[5];
    const float* bn1b = (const float*)d_in[6];
    const float* bn2g = (const float*)d_in[7];
    const float* bn2b = (const float*)d_in[8];
    float* out = (float*)d_out;
    (void)in_sizes; (void)n_in; (void)out_size;

    k0_proj<<<NT0, 256>>>(atom, W);
    k1_pass<false><<<KGB, 256>>>(nbr, idx, W, bvec);   // BN1 stats
    k2_fin<<<CO, 256>>>(bn1g, bn1b);
    k1_pass<true><<<KGB, 256>>>(nbr, idx, W, bvec);    // recompute + act + atom sum
    k4_fin<<<AFEA, 256>>>(bn2g, bn2b);
    k5_out<<<(NATOM * AFEA + 255) / 256, 256>>>(atom, out);
}